// round 9
// baseline (speedup 1.0000x reference)
#include <cuda_runtime.h>
#include <cuda_bf16.h>
#include <math.h>

#define N_USERS 50000
#define N_ENT   100000
#define DIMS    64
#define N_REL   16
#define E_KG    1500000
#define E_IN    1000000
#define RSQRT_DK 0.17677669529663687f   /* 1/sqrt(32) */

#define NB_ENT (N_ENT / 8)     /* 12500 entity blocks (8 warps = 8 rows each) */
#define NB_USR (N_USERS / 8)   /*  6250 user blocks */

// ---------------- static device scratch (no runtime allocation) ----------------
__device__ __nv_bfloat162 g_P[N_ENT * 32];   // entity_emb @ W_Q, bf16 (scores only)
__device__ float g_ent0[N_ENT * DIMS];       // layer-1 entity output
__device__ float g_usr0[N_USERS * DIMS];     // layer-1 user output

// CSR structures (built once per call)
__device__ int g_kg_row[N_ENT + 1];
__device__ int g_kg_cur[N_ENT];              // counter, then cursor
__device__ unsigned g_kg_pk[E_KG];           // tail | (rel<<20)
__device__ int g_iu_row[N_USERS + 1];
__device__ int g_iu_cur[N_USERS];
__device__ int2 g_iu_pk[E_IN];               // {item, w bits}
__device__ int g_ii_row[N_ENT + 1];
__device__ int g_ii_cur[N_ENT];
__device__ int2 g_ii_pk[E_IN];               // {user, w bits}

// ---------------- helpers ----------------
// Reduce within each 16-lane half of the warp (butterfly). Every lane ends
// with the sum over its half.
__device__ __forceinline__ float half_reduce(float v) {
    v += __shfl_xor_sync(0xffffffffu, v, 1);
    v += __shfl_xor_sync(0xffffffffu, v, 2);
    v += __shfl_xor_sync(0xffffffffu, v, 4);
    v += __shfl_xor_sync(0xffffffffu, v, 8);
    return v;
}

// ---------------- CSR build ----------------
__global__ void zero_cnt_k(int* __restrict__ a, int na, int* __restrict__ b, int nb,
                           int* __restrict__ c, int nc) {
    int i = blockIdx.x * blockDim.x + threadIdx.x;
    int stride = gridDim.x * blockDim.x;
    int nab = na + nb, tot = nab + nc;
    for (; i < tot; i += stride) {
        if (i < na) a[i] = 0;
        else if (i < nab) b[i - na] = 0;
        else c[i - nab] = 0;
    }
}

__global__ void hist_k(const int* __restrict__ eidx, const int* __restrict__ iedge,
                       int* __restrict__ kg_cnt, int* __restrict__ iu_cnt,
                       int* __restrict__ ii_cnt) {
    int stride = gridDim.x * blockDim.x;
    for (int i = blockIdx.x * blockDim.x + threadIdx.x; i < E_KG; i += stride)
        atomicAdd(&kg_cnt[eidx[i]], 1);
    for (int i = blockIdx.x * blockDim.x + threadIdx.x; i < E_IN; i += stride) {
        atomicAdd(&iu_cnt[iedge[i]], 1);
        atomicAdd(&ii_cnt[iedge[E_IN + i]], 1);
    }
}

// Three one-block exclusive scans in one launch (block 0: kg, 1: iu, 2: ii).
// cnt aliases cur (each element read by the owning thread before overwrite).
__global__ void __launch_bounds__(1024) scan3_k(int* __restrict__ kg_cur,
                                                int* __restrict__ kg_row,
                                                int* __restrict__ iu_cur,
                                                int* __restrict__ iu_row,
                                                int* __restrict__ ii_cur,
                                                int* __restrict__ ii_row) {
    const int* cnt; int* row; int* cur; int n;
    if (blockIdx.x == 0)      { cnt = kg_cur; row = kg_row; cur = kg_cur; n = N_ENT; }
    else if (blockIdx.x == 1) { cnt = iu_cur; row = iu_row; cur = iu_cur; n = N_USERS; }
    else                      { cnt = ii_cur; row = ii_row; cur = ii_cur; n = N_ENT; }

    __shared__ int wsum[32];
    __shared__ int base_s;
    int tid = threadIdx.x;
    int lane = tid & 31, w = tid >> 5;
    if (tid == 0) base_s = 0;
    __syncthreads();
    for (int b = 0; b < n; b += 4096) {
        int i = b + tid * 4;
        int4 v = (i + 3 < n) ? *(const int4*)&cnt[i] : make_int4(0, 0, 0, 0);
        int tsum = v.x + v.y + v.z + v.w;
        int x = tsum;
        #pragma unroll
        for (int o = 1; o < 32; o <<= 1) {
            int y = __shfl_up_sync(0xffffffffu, x, o);
            if (lane >= o) x += y;
        }
        if (lane == 31) wsum[w] = x;
        __syncthreads();
        if (w == 0) {
            int s = wsum[lane];
            #pragma unroll
            for (int o = 1; o < 32; o <<= 1) {
                int y = __shfl_up_sync(0xffffffffu, s, o);
                if (lane >= o) s += y;
            }
            wsum[lane] = s;
        }
        __syncthreads();
        int excl = x - tsum + (w ? wsum[w - 1] : 0) + base_s;
        if (i + 3 < n) {
            int4 o4 = make_int4(excl, excl + v.x, excl + v.x + v.y,
                                excl + v.x + v.y + v.z);
            *(int4*)&row[i] = o4;
            *(int4*)&cur[i] = o4;
        }
        __syncthreads();
        if (tid == 1023) base_s = excl + tsum;
        __syncthreads();
    }
    if (tid == 0) row[n] = base_s;
}

__global__ void scatter_k(const int* __restrict__ eidx, const int* __restrict__ etype,
                          const int* __restrict__ iedge, const float* __restrict__ iw,
                          int* __restrict__ kg_cur, unsigned* __restrict__ kg_pk,
                          int* __restrict__ iu_cur, int2* __restrict__ iu_pk,
                          int* __restrict__ ii_cur, int2* __restrict__ ii_pk) {
    int stride = gridDim.x * blockDim.x;
    for (int i = blockIdx.x * blockDim.x + threadIdx.x; i < E_KG; i += stride) {
        int hd = eidx[i];
        unsigned tl = (unsigned)eidx[E_KG + i];
        unsigned rt = (unsigned)(etype[i] - 1);
        int pos = atomicAdd(&kg_cur[hd], 1);
        kg_pk[pos] = tl | (rt << 20);
    }
    for (int i = blockIdx.x * blockDim.x + threadIdx.x; i < E_IN; i += stride) {
        int u = iedge[i];
        int it = iedge[E_IN + i];
        int wb = __float_as_int(iw[i]);
        int p1 = atomicAdd(&iu_cur[u], 1);
        iu_pk[p1] = make_int2(it, wb);
        int p2 = atomicAdd(&ii_cur[it], 1);
        ii_pk[p2] = make_int2(u, wb);
    }
}

// ---------------- per-layer kernels ----------------
// P[r,:] = X[r,:] @ W (64x64), output bf16. 256 threads = 16 rows x 16 col-quads.
__global__ void __launch_bounds__(256) gemm_k(const float* __restrict__ X,
                                              const float* __restrict__ W,
                                              __nv_bfloat162* __restrict__ P) {
    __shared__ float sW[64 * 64];
    __shared__ float srow[16][64];
    int tid = threadIdx.x;
    #pragma unroll
    for (int i = 0; i < 16; i++) sW[tid + i * 256] = W[tid + i * 256];
    const float4* X4 = (const float4*)(X + (size_t)blockIdx.x * 16 * 64);
    ((float4*)&srow[0][0])[tid] = X4[tid];
    __syncthreads();
    int r  = tid >> 4;
    int cq = (tid & 15) * 4;
    float4 acc = make_float4(0.f, 0.f, 0.f, 0.f);
    #pragma unroll
    for (int d = 0; d < 64; d++) {
        float a = srow[r][d];
        float4 b = *(const float4*)&sW[d * 64 + cq];
        acc.x += a * b.x; acc.y += a * b.y; acc.z += a * b.z; acc.w += a * b.w;
    }
    size_t o = ((size_t)blockIdx.x * 16 + r) * 32 + (cq >> 1);
    P[o]     = __float22bfloat162_rn(make_float2(acc.x, acc.y));
    P[o + 1] = __float22bfloat162_rn(make_float2(acc.z, acc.w));
}

// Fused node update: blocks [0, NB_ENT) do entities, [NB_ENT, NB_ENT+NB_USR) users.
// One warp per row; lane l owns dims 2l, 2l+1.
// FINAL=0: write new embedding to ent_out/usr_out.
// FINAL=1: write (orig + prev + new)/3 (the mean epilogue) instead.
template <int FINAL>
__global__ void __launch_bounds__(256) node_k(const int* __restrict__ kg_row,
                                              const unsigned* __restrict__ kg_pk,
                                              const int* __restrict__ ii_row,
                                              const int2* __restrict__ ii_pk,
                                              const int* __restrict__ iu_row,
                                              const int2* __restrict__ iu_pk,
                                              const __nv_bfloat162* __restrict__ P,
                                              const float* __restrict__ ent_cur,
                                              const float* __restrict__ usr_cur,
                                              const float* __restrict__ relemb,
                                              const float* __restrict__ ent_p0,
                                              const float* __restrict__ usr_p0,
                                              float* __restrict__ ent_out,
                                              float* __restrict__ usr_out) {
    int tid  = threadIdx.x;
    int lane = tid & 31;
    int d0   = lane * 2;
    const float c3 = 1.0f / 3.0f;

    if (blockIdx.x < NB_ENT) {
        // ---------------- entity path ----------------
        __shared__ float srel[N_REL * DIMS];
        #pragma unroll
        for (int i = 0; i < 4; i++) srel[tid + i * 256] = relemb[tid + i * 256];
        __syncthreads();

        int row = blockIdx.x * 8 + (tid >> 5);
        float2 ph = __bfloat1622float2(P[(size_t)row * 32 + lane]);

        float2 acc = make_float2(0.f, 0.f);
        float ssum = 0.f;
        int s = kg_row[row], e = kg_row[row + 1];
        int j = s;
        for (; j + 1 < e; j += 2) {
            unsigned pk0 = kg_pk[j], pk1 = kg_pk[j + 1];
            int tl0 = (int)(pk0 & 0xFFFFFu), rt0 = (int)(pk0 >> 20);
            int tl1 = (int)(pk1 & 0xFFFFFu), rt1 = (int)(pk1 >> 20);
            float2 pt0 = __bfloat1622float2(P[(size_t)tl0 * 32 + lane]);
            float2 pt1 = __bfloat1622float2(P[(size_t)tl1 * 32 + lane]);
            float2 rv0 = *(const float2*)&srel[rt0 * 64 + d0];
            float2 rv1 = *(const float2*)&srel[rt1 * 64 + d0];
            float2 te0 = *(const float2*)&ent_cur[(size_t)tl0 * 64 + d0];
            float2 te1 = *(const float2*)&ent_cur[(size_t)tl1 * 64 + d0];
            float p0 = ph.x * pt0.x * rv0.x + ph.y * pt0.y * rv0.y;
            float p1 = ph.x * pt1.x * rv1.x + ph.y * pt1.y * rv1.y;
            float r0 = half_reduce(p0);
            float r1 = half_reduce(p1);
            float ex0 = __expf(r0 * RSQRT_DK);
            float ex1 = __expf(r1 * RSQRT_DK);
            ssum += ex0 + ex1;
            acc.x += ex0 * te0.x * rv0.x + ex1 * te1.x * rv1.x;
            acc.y += ex0 * te0.y * rv0.y + ex1 * te1.y * rv1.y;
        }
        if (j < e) {
            unsigned pk0 = kg_pk[j];
            int tl0 = (int)(pk0 & 0xFFFFFu), rt0 = (int)(pk0 >> 20);
            float2 pt0 = __bfloat1622float2(P[(size_t)tl0 * 32 + lane]);
            float2 rv0 = *(const float2*)&srel[rt0 * 64 + d0];
            float2 te0 = *(const float2*)&ent_cur[(size_t)tl0 * 64 + d0];
            float p0 = ph.x * pt0.x * rv0.x + ph.y * pt0.y * rv0.y;
            float r0 = half_reduce(p0);
            float ex0 = __expf(r0 * RSQRT_DK);
            ssum += ex0;
            acc.x += ex0 * te0.x * rv0.x;
            acc.y += ex0 * te0.y * rv0.y;
        }
        float invs = (ssum > 0.f) ? (1.f / ssum) : 1.f;
        acc.x *= invs; acc.y *= invs;

        // L2 normalize over all 64 dims
        float s2 = acc.x * acc.x + acc.y * acc.y;
        s2 = half_reduce(s2);
        s2 += __shfl_xor_sync(0xffffffffu, s2, 16);
        float invn = 1.0f / fmaxf(sqrtf(s2), 1e-12f);
        acc.x *= invn; acc.y *= invn;

        // user -> entity aggregation
        int si = ii_row[row], ei = ii_row[row + 1];
        #pragma unroll 2
        for (int k = si; k < ei; k++) {
            int2 p = ii_pk[k];
            float w = __int_as_float(p.y);
            float2 uv = *(const float2*)&usr_cur[(size_t)p.x * 64 + d0];
            acc.x += w * uv.x;
            acc.y += w * uv.y;
        }
        if (FINAL) {
            // ent_cur here is the layer-1 output; ent_p0 is the original input.
            float2 a0 = *(const float2*)&ent_cur[(size_t)row * 64 + d0];
            float2 a1 = *(const float2*)&ent_p0[(size_t)row * 64 + d0];
            acc.x = (a0.x + a1.x + acc.x) * c3;
            acc.y = (a0.y + a1.y + acc.y) * c3;
        }
        *(float2*)&ent_out[(size_t)row * 64 + d0] = acc;
    } else {
        // ---------------- user path ----------------
        int row = (blockIdx.x - NB_ENT) * 8 + (tid >> 5);
        float2 acc = make_float2(0.f, 0.f);
        int s = iu_row[row], e = iu_row[row + 1];
        #pragma unroll 2
        for (int k = s; k < e; k++) {
            int2 p = iu_pk[k];
            float w = __int_as_float(p.y);
            float2 ev = *(const float2*)&ent_cur[(size_t)p.x * 64 + d0];
            acc.x += w * ev.x;
            acc.y += w * ev.y;
        }
        if (FINAL) {
            float2 a0 = *(const float2*)&usr_cur[(size_t)row * 64 + d0];  // layer-1 user
            float2 a1 = *(const float2*)&usr_p0[(size_t)row * 64 + d0];   // original input
            acc.x = (a0.x + a1.x + acc.x) * c3;
            acc.y = (a0.y + a1.y + acc.y) * c3;
        }
        *(float2*)&usr_out[(size_t)row * 64 + d0] = acc;
    }
}

// ---------------- launcher ----------------
extern "C" void kernel_launch(void* const* d_in, const int* in_sizes, int n_in,
                              void* d_out, int out_size) {
    const float* user_emb   = (const float*)d_in[1];
    const float* entity_emb = (const float*)d_in[2];
    const int*   inter_edge = (const int*)d_in[3];
    const float* inter_w    = (const float*)d_in[4];
    const int*   edge_index = (const int*)d_in[5];
    const int*   edge_type  = (const int*)d_in[6];
    const float* rel_emb    = (const float*)d_in[7];
    const float* W_Q        = (const float*)d_in[8];
    float* out = (float*)d_out;
    float* out_usr = out;
    float* out_ent = out + (size_t)N_USERS * DIMS;

    __nv_bfloat162* p_P;
    float *p_ent0, *p_usr0;
    int *p_kg_row, *p_kg_cur, *p_iu_row, *p_iu_cur, *p_ii_row, *p_ii_cur;
    unsigned* p_kg_pk;
    int2 *p_iu_pk, *p_ii_pk;
    cudaGetSymbolAddress((void**)&p_P,      g_P);
    cudaGetSymbolAddress((void**)&p_ent0,   g_ent0);
    cudaGetSymbolAddress((void**)&p_usr0,   g_usr0);
    cudaGetSymbolAddress((void**)&p_kg_row, g_kg_row);
    cudaGetSymbolAddress((void**)&p_kg_cur, g_kg_cur);
    cudaGetSymbolAddress((void**)&p_kg_pk,  g_kg_pk);
    cudaGetSymbolAddress((void**)&p_iu_row, g_iu_row);
    cudaGetSymbolAddress((void**)&p_iu_cur, g_iu_cur);
    cudaGetSymbolAddress((void**)&p_iu_pk,  g_iu_pk);
    cudaGetSymbolAddress((void**)&p_ii_row, g_ii_row);
    cudaGetSymbolAddress((void**)&p_ii_cur, g_ii_cur);
    cudaGetSymbolAddress((void**)&p_ii_pk,  g_ii_pk);

    const int TB = 256;
    const int NB_NODE = NB_ENT + NB_USR;   // 18750

    // ---- CSR build (shared by both layers) ----
    zero_cnt_k<<<512, TB>>>(p_kg_cur, N_ENT, p_iu_cur, N_USERS, p_ii_cur, N_ENT);
    hist_k<<<4096, TB>>>(edge_index, inter_edge, p_kg_cur, p_iu_cur, p_ii_cur);
    scan3_k<<<3, 1024>>>(p_kg_cur, p_kg_row, p_iu_cur, p_iu_row, p_ii_cur, p_ii_row);
    scatter_k<<<4096, TB>>>(edge_index, edge_type, inter_edge, inter_w,
                            p_kg_cur, p_kg_pk, p_iu_cur, p_iu_pk, p_ii_cur, p_ii_pk);

    // ---- layer 1 ----
    gemm_k<<<N_ENT / 16, TB>>>(entity_emb, W_Q, p_P);
    node_k<0><<<NB_NODE, TB>>>(p_kg_row, p_kg_pk, p_ii_row, p_ii_pk, p_iu_row, p_iu_pk,
                               p_P, entity_emb, user_emb, rel_emb,
                               nullptr, nullptr, p_ent0, p_usr0);

    // ---- layer 2 (writes the 3-layer mean directly to out) ----
    gemm_k<<<N_ENT / 16, TB>>>(p_ent0, W_Q, p_P);
    node_k<1><<<NB_NODE, TB>>>(p_kg_row, p_kg_pk, p_ii_row, p_ii_pk, p_iu_row, p_iu_pk,
                               p_P, p_ent0, p_usr0, rel_emb,
                               entity_emb, user_emb, out_ent, out_usr);
}

// round 10
// speedup vs baseline: 1.0184x; 1.0184x over previous
#include <cuda_runtime.h>
#include <cuda_bf16.h>
#include <math.h>

#define N_USERS 50000
#define N_ENT   100000
#define DIMS    64
#define N_REL   16
#define E_KG    1500000
#define E_IN    1000000
#define RSQRT_DK 0.17677669529663687f   /* 1/sqrt(32) */

#define NB_ENT (N_ENT / 8)     /* 12500 entity blocks (8 warps = 8 rows each) */
#define NB_USR (N_USERS / 8)   /*  6250 user blocks */

// ---------------- static device scratch (no runtime allocation) ----------------
__device__ __nv_bfloat162 g_P[N_ENT * 32];   // entity_emb @ W_Q, bf16 (scores only)
__device__ float g_ent0[N_ENT * DIMS];       // layer-1 entity output
__device__ float g_usr0[N_USERS * DIMS];     // layer-1 user output

// CSR structures (built once per call)
__device__ int g_kg_row[N_ENT + 1];
__device__ int g_kg_cur[N_ENT];              // counter, then cursor
__device__ unsigned g_kg_pk[E_KG];           // tail | (rel<<20)
__device__ int g_iu_row[N_USERS + 1];
__device__ int g_iu_cur[N_USERS];
__device__ int2 g_iu_pk[E_IN];               // {item, w bits}
__device__ int g_ii_row[N_ENT + 1];
__device__ int g_ii_cur[N_ENT];
__device__ int2 g_ii_pk[E_IN];               // {user, w bits}

// ---------------- CSR build ----------------
__global__ void zero_cnt_k(int* __restrict__ a, int na, int* __restrict__ b, int nb,
                           int* __restrict__ c, int nc) {
    int i = blockIdx.x * blockDim.x + threadIdx.x;
    int stride = gridDim.x * blockDim.x;
    int nab = na + nb, tot = nab + nc;
    for (; i < tot; i += stride) {
        if (i < na) a[i] = 0;
        else if (i < nab) b[i - na] = 0;
        else c[i - nab] = 0;
    }
}

// Batched histogram: int4 loads, 4 independent atomics per thread per step.
__global__ void hist_k(const int* __restrict__ eidx, const int* __restrict__ iedge,
                       int* __restrict__ kg_cnt, int* __restrict__ iu_cnt,
                       int* __restrict__ ii_cnt) {
    int stride = gridDim.x * blockDim.x * 4;
    for (int base = (blockIdx.x * blockDim.x + threadIdx.x) * 4; base < E_KG;
         base += stride) {
        int4 h = *(const int4*)&eidx[base];
        atomicAdd(&kg_cnt[h.x], 1);
        atomicAdd(&kg_cnt[h.y], 1);
        atomicAdd(&kg_cnt[h.z], 1);
        atomicAdd(&kg_cnt[h.w], 1);
    }
    for (int base = (blockIdx.x * blockDim.x + threadIdx.x) * 4; base < E_IN;
         base += stride) {
        int4 u  = *(const int4*)&iedge[base];
        int4 it = *(const int4*)&iedge[E_IN + base];
        atomicAdd(&iu_cnt[u.x], 1);
        atomicAdd(&iu_cnt[u.y], 1);
        atomicAdd(&iu_cnt[u.z], 1);
        atomicAdd(&iu_cnt[u.w], 1);
        atomicAdd(&ii_cnt[it.x], 1);
        atomicAdd(&ii_cnt[it.y], 1);
        atomicAdd(&ii_cnt[it.z], 1);
        atomicAdd(&ii_cnt[it.w], 1);
    }
}

// Three one-block exclusive scans in one launch (block 0: kg, 1: iu, 2: ii).
// cnt aliases cur (each element read by the owning thread before overwrite).
__global__ void __launch_bounds__(1024) scan3_k(int* __restrict__ kg_cur,
                                                int* __restrict__ kg_row,
                                                int* __restrict__ iu_cur,
                                                int* __restrict__ iu_row,
                                                int* __restrict__ ii_cur,
                                                int* __restrict__ ii_row) {
    const int* cnt; int* row; int* cur; int n;
    if (blockIdx.x == 0)      { cnt = kg_cur; row = kg_row; cur = kg_cur; n = N_ENT; }
    else if (blockIdx.x == 1) { cnt = iu_cur; row = iu_row; cur = iu_cur; n = N_USERS; }
    else                      { cnt = ii_cur; row = ii_row; cur = ii_cur; n = N_ENT; }

    __shared__ int wsum[32];
    __shared__ int base_s;
    int tid = threadIdx.x;
    int lane = tid & 31, w = tid >> 5;
    if (tid == 0) base_s = 0;
    __syncthreads();
    for (int b = 0; b < n; b += 4096) {
        int i = b + tid * 4;
        int4 v = (i + 3 < n) ? *(const int4*)&cnt[i] : make_int4(0, 0, 0, 0);
        int tsum = v.x + v.y + v.z + v.w;
        int x = tsum;
        #pragma unroll
        for (int o = 1; o < 32; o <<= 1) {
            int y = __shfl_up_sync(0xffffffffu, x, o);
            if (lane >= o) x += y;
        }
        if (lane == 31) wsum[w] = x;
        __syncthreads();
        if (w == 0) {
            int s = wsum[lane];
            #pragma unroll
            for (int o = 1; o < 32; o <<= 1) {
                int y = __shfl_up_sync(0xffffffffu, s, o);
                if (lane >= o) s += y;
            }
            wsum[lane] = s;
        }
        __syncthreads();
        int excl = x - tsum + (w ? wsum[w - 1] : 0) + base_s;
        if (i + 3 < n) {
            int4 o4 = make_int4(excl, excl + v.x, excl + v.x + v.y,
                                excl + v.x + v.y + v.z);
            *(int4*)&row[i] = o4;
            *(int4*)&cur[i] = o4;
        }
        __syncthreads();
        if (tid == 1023) base_s = excl + tsum;
        __syncthreads();
    }
    if (tid == 0) row[n] = base_s;
}

// Batched scatter: 4 edges per thread per step -> 4 independent atomic
// round-trips in flight before the dependent stores.
__global__ void scatter_k(const int* __restrict__ eidx, const int* __restrict__ etype,
                          const int* __restrict__ iedge, const float* __restrict__ iw,
                          int* __restrict__ kg_cur, unsigned* __restrict__ kg_pk,
                          int* __restrict__ iu_cur, int2* __restrict__ iu_pk,
                          int* __restrict__ ii_cur, int2* __restrict__ ii_pk) {
    int stride = gridDim.x * blockDim.x * 4;
    for (int base = (blockIdx.x * blockDim.x + threadIdx.x) * 4; base < E_KG;
         base += stride) {
        int4 hd = *(const int4*)&eidx[base];
        int4 tl = *(const int4*)&eidx[E_KG + base];
        int4 rt = *(const int4*)&etype[base];
        int p0 = atomicAdd(&kg_cur[hd.x], 1);
        int p1 = atomicAdd(&kg_cur[hd.y], 1);
        int p2 = atomicAdd(&kg_cur[hd.z], 1);
        int p3 = atomicAdd(&kg_cur[hd.w], 1);
        kg_pk[p0] = (unsigned)tl.x | ((unsigned)(rt.x - 1) << 20);
        kg_pk[p1] = (unsigned)tl.y | ((unsigned)(rt.y - 1) << 20);
        kg_pk[p2] = (unsigned)tl.z | ((unsigned)(rt.z - 1) << 20);
        kg_pk[p3] = (unsigned)tl.w | ((unsigned)(rt.w - 1) << 20);
    }
    for (int base = (blockIdx.x * blockDim.x + threadIdx.x) * 4; base < E_IN;
         base += stride) {
        int4 u  = *(const int4*)&iedge[base];
        int4 it = *(const int4*)&iedge[E_IN + base];
        float4 w = *(const float4*)&iw[base];
        int a0 = atomicAdd(&iu_cur[u.x], 1);
        int a1 = atomicAdd(&iu_cur[u.y], 1);
        int a2 = atomicAdd(&iu_cur[u.z], 1);
        int a3 = atomicAdd(&iu_cur[u.w], 1);
        int b0 = atomicAdd(&ii_cur[it.x], 1);
        int b1 = atomicAdd(&ii_cur[it.y], 1);
        int b2 = atomicAdd(&ii_cur[it.z], 1);
        int b3 = atomicAdd(&ii_cur[it.w], 1);
        iu_pk[a0] = make_int2(it.x, __float_as_int(w.x));
        iu_pk[a1] = make_int2(it.y, __float_as_int(w.y));
        iu_pk[a2] = make_int2(it.z, __float_as_int(w.z));
        iu_pk[a3] = make_int2(it.w, __float_as_int(w.w));
        ii_pk[b0] = make_int2(u.x, __float_as_int(w.x));
        ii_pk[b1] = make_int2(u.y, __float_as_int(w.y));
        ii_pk[b2] = make_int2(u.z, __float_as_int(w.z));
        ii_pk[b3] = make_int2(u.w, __float_as_int(w.w));
    }
}

// ---------------- per-layer kernels ----------------
// P[r,:] = X[r,:] @ W (64x64), output bf16. 256 threads = 16 rows x 16 col-quads.
__global__ void __launch_bounds__(256) gemm_k(const float* __restrict__ X,
                                              const float* __restrict__ W,
                                              __nv_bfloat162* __restrict__ P) {
    __shared__ float sW[64 * 64];
    __shared__ float srow[16][64];
    int tid = threadIdx.x;
    #pragma unroll
    for (int i = 0; i < 16; i++) sW[tid + i * 256] = W[tid + i * 256];
    const float4* X4 = (const float4*)(X + (size_t)blockIdx.x * 16 * 64);
    ((float4*)&srow[0][0])[tid] = X4[tid];
    __syncthreads();
    int r  = tid >> 4;
    int cq = (tid & 15) * 4;
    float4 acc = make_float4(0.f, 0.f, 0.f, 0.f);
    #pragma unroll
    for (int d = 0; d < 64; d++) {
        float a = srow[r][d];
        float4 b = *(const float4*)&sW[d * 64 + cq];
        acc.x += a * b.x; acc.y += a * b.y; acc.z += a * b.z; acc.w += a * b.w;
    }
    size_t o = ((size_t)blockIdx.x * 16 + r) * 32 + (cq >> 1);
    P[o]     = __float22bfloat162_rn(make_float2(acc.x, acc.y));
    P[o + 1] = __float22bfloat162_rn(make_float2(acc.z, acc.w));
}

__device__ __forceinline__ float4 ld_P4(const __nv_bfloat162* __restrict__ P,
                                        int row, int l) {
    // dims 4l..4l+3 of P row (bf16) as float4
    uint2 raw = *(const uint2*)(P + (size_t)row * 32 + l * 2);
    __nv_bfloat162 b0 = *(__nv_bfloat162*)&raw.x;
    __nv_bfloat162 b1 = *(__nv_bfloat162*)&raw.y;
    float2 f0 = __bfloat1622float2(b0);
    float2 f1 = __bfloat1622float2(b1);
    return make_float4(f0.x, f0.y, f1.x, f1.y);
}

// Fused node update: blocks [0, NB_ENT) do entities, [NB_ENT, NB_ENT+NB_USR) users.
// One warp per row. Edge loops process 2 edges per iteration: lanes 0-15 handle
// edge j, lanes 16-31 edge j+1. Lane owns dims 4*(lane&15)..+3 (float4).
// FINAL=0: write new embedding. FINAL=1: write (orig + prev + new)/3.
template <int FINAL>
__global__ void __launch_bounds__(256) node_k(const int* __restrict__ kg_row,
                                              const unsigned* __restrict__ kg_pk,
                                              const int* __restrict__ ii_row,
                                              const int2* __restrict__ ii_pk,
                                              const int* __restrict__ iu_row,
                                              const int2* __restrict__ iu_pk,
                                              const __nv_bfloat162* __restrict__ P,
                                              const float* __restrict__ ent_cur,
                                              const float* __restrict__ usr_cur,
                                              const float* __restrict__ relemb,
                                              const float* __restrict__ ent_p0,
                                              const float* __restrict__ usr_p0,
                                              float* __restrict__ ent_out,
                                              float* __restrict__ usr_out) {
    int tid  = threadIdx.x;
    int lane = tid & 31;
    int half = lane >> 4;          // which edge of the pair
    int l    = lane & 15;          // lane within edge
    int d0   = l * 4;              // dims owned
    const float c3 = 1.0f / 3.0f;

    if (blockIdx.x < NB_ENT) {
        // ---------------- entity path ----------------
        __shared__ float srel[N_REL * DIMS];
        #pragma unroll
        for (int i = 0; i < 4; i++) srel[tid + i * 256] = relemb[tid + i * 256];
        __syncthreads();

        int row = blockIdx.x * 8 + (tid >> 5);
        float4 ph = ld_P4(P, row, l);

        float4 acc = make_float4(0.f, 0.f, 0.f, 0.f);
        float ssum = 0.f;
        int s = kg_row[row], e = kg_row[row + 1];
        for (int j = s; j < e; j += 2) {
            int idx = j + half;
            bool valid = idx < e;
            int idxc = valid ? idx : (e - 1);
            unsigned pk = kg_pk[idxc];
            int tl = (int)(pk & 0xFFFFFu);
            int rt = (int)(pk >> 20);
            float4 pt = ld_P4(P, tl, l);
            float4 rv = *(const float4*)&srel[rt * 64 + d0];
            float4 te = *(const float4*)&ent_cur[(size_t)tl * 64 + d0];
            float part = ph.x * pt.x * rv.x + ph.y * pt.y * rv.y
                       + ph.z * pt.z * rv.z + ph.w * pt.w * rv.w;
            // reduce over 8 lanes (one head = 8 lanes: dims 0-31 / 32-63)
            part += __shfl_xor_sync(0xffffffffu, part, 1);
            part += __shfl_xor_sync(0xffffffffu, part, 2);
            part += __shfl_xor_sync(0xffffffffu, part, 4);
            float ex = valid ? __expf(part * RSQRT_DK) : 0.f;
            ssum += ex;
            acc.x += ex * te.x * rv.x;
            acc.y += ex * te.y * rv.y;
            acc.z += ex * te.z * rv.z;
            acc.w += ex * te.w * rv.w;
        }
        // combine the two edge-halves (lanes l and l+16 own the same dims)
        acc.x += __shfl_xor_sync(0xffffffffu, acc.x, 16);
        acc.y += __shfl_xor_sync(0xffffffffu, acc.y, 16);
        acc.z += __shfl_xor_sync(0xffffffffu, acc.z, 16);
        acc.w += __shfl_xor_sync(0xffffffffu, acc.w, 16);
        ssum  += __shfl_xor_sync(0xffffffffu, ssum, 16);

        float invs = (ssum > 0.f) ? (1.f / ssum) : 1.f;
        acc.x *= invs; acc.y *= invs; acc.z *= invs; acc.w *= invs;

        // L2 normalize over all 64 dims (each 16-lane half spans all dims)
        float s2 = acc.x * acc.x + acc.y * acc.y + acc.z * acc.z + acc.w * acc.w;
        s2 += __shfl_xor_sync(0xffffffffu, s2, 1);
        s2 += __shfl_xor_sync(0xffffffffu, s2, 2);
        s2 += __shfl_xor_sync(0xffffffffu, s2, 4);
        s2 += __shfl_xor_sync(0xffffffffu, s2, 8);
        float invn = 1.0f / fmaxf(sqrtf(s2), 1e-12f);
        acc.x *= invn; acc.y *= invn; acc.z *= invn; acc.w *= invn;

        // user -> entity aggregation (pair-split into acc2, combined after)
        float4 acc2 = make_float4(0.f, 0.f, 0.f, 0.f);
        int si = ii_row[row], ei = ii_row[row + 1];
        for (int k = si; k < ei; k += 2) {
            int idx = k + half;
            bool valid = idx < ei;
            int idxc = valid ? idx : (ei - 1);
            int2 p = ii_pk[idxc];
            float w = valid ? __int_as_float(p.y) : 0.f;
            float4 uv = *(const float4*)&usr_cur[(size_t)p.x * 64 + d0];
            acc2.x += w * uv.x; acc2.y += w * uv.y;
            acc2.z += w * uv.z; acc2.w += w * uv.w;
        }
        acc2.x += __shfl_xor_sync(0xffffffffu, acc2.x, 16);
        acc2.y += __shfl_xor_sync(0xffffffffu, acc2.y, 16);
        acc2.z += __shfl_xor_sync(0xffffffffu, acc2.z, 16);
        acc2.w += __shfl_xor_sync(0xffffffffu, acc2.w, 16);
        acc.x += acc2.x; acc.y += acc2.y; acc.z += acc2.z; acc.w += acc2.w;

        if (half == 0) {
            if (FINAL) {
                // ent_cur = layer-1 output; ent_p0 = original input
                float4 a0 = *(const float4*)&ent_cur[(size_t)row * 64 + d0];
                float4 a1 = *(const float4*)&ent_p0[(size_t)row * 64 + d0];
                acc.x = (a0.x + a1.x + acc.x) * c3;
                acc.y = (a0.y + a1.y + acc.y) * c3;
                acc.z = (a0.z + a1.z + acc.z) * c3;
                acc.w = (a0.w + a1.w + acc.w) * c3;
            }
            *(float4*)&ent_out[(size_t)row * 64 + d0] = acc;
        }
    } else {
        // ---------------- user path ----------------
        int row = (blockIdx.x - NB_ENT) * 8 + (tid >> 5);
        float4 acc = make_float4(0.f, 0.f, 0.f, 0.f);
        int s = iu_row[row], e = iu_row[row + 1];
        for (int k = s; k < e; k += 2) {
            int idx = k + half;
            bool valid = idx < e;
            int idxc = valid ? idx : (e - 1);
            int2 p = iu_pk[idxc];
            float w = valid ? __int_as_float(p.y) : 0.f;
            float4 ev = *(const float4*)&ent_cur[(size_t)p.x * 64 + d0];
            acc.x += w * ev.x; acc.y += w * ev.y;
            acc.z += w * ev.z; acc.w += w * ev.w;
        }
        acc.x += __shfl_xor_sync(0xffffffffu, acc.x, 16);
        acc.y += __shfl_xor_sync(0xffffffffu, acc.y, 16);
        acc.z += __shfl_xor_sync(0xffffffffu, acc.z, 16);
        acc.w += __shfl_xor_sync(0xffffffffu, acc.w, 16);

        if (half == 0) {
            if (FINAL) {
                float4 a0 = *(const float4*)&usr_cur[(size_t)row * 64 + d0]; // layer-1
                float4 a1 = *(const float4*)&usr_p0[(size_t)row * 64 + d0];  // original
                acc.x = (a0.x + a1.x + acc.x) * c3;
                acc.y = (a0.y + a1.y + acc.y) * c3;
                acc.z = (a0.z + a1.z + acc.z) * c3;
                acc.w = (a0.w + a1.w + acc.w) * c3;
            }
            *(float4*)&usr_out[(size_t)row * 64 + d0] = acc;
        }
    }
}

// ---------------- launcher ----------------
extern "C" void kernel_launch(void* const* d_in, const int* in_sizes, int n_in,
                              void* d_out, int out_size) {
    const float* user_emb   = (const float*)d_in[1];
    const float* entity_emb = (const float*)d_in[2];
    const int*   inter_edge = (const int*)d_in[3];
    const float* inter_w    = (const float*)d_in[4];
    const int*   edge_index = (const int*)d_in[5];
    const int*   edge_type  = (const int*)d_in[6];
    const float* rel_emb    = (const float*)d_in[7];
    const float* W_Q        = (const float*)d_in[8];
    float* out = (float*)d_out;
    float* out_usr = out;
    float* out_ent = out + (size_t)N_USERS * DIMS;

    __nv_bfloat162* p_P;
    float *p_ent0, *p_usr0;
    int *p_kg_row, *p_kg_cur, *p_iu_row, *p_iu_cur, *p_ii_row, *p_ii_cur;
    unsigned* p_kg_pk;
    int2 *p_iu_pk, *p_ii_pk;
    cudaGetSymbolAddress((void**)&p_P,      g_P);
    cudaGetSymbolAddress((void**)&p_ent0,   g_ent0);
    cudaGetSymbolAddress((void**)&p_usr0,   g_usr0);
    cudaGetSymbolAddress((void**)&p_kg_row, g_kg_row);
    cudaGetSymbolAddress((void**)&p_kg_cur, g_kg_cur);
    cudaGetSymbolAddress((void**)&p_kg_pk,  g_kg_pk);
    cudaGetSymbolAddress((void**)&p_iu_row, g_iu_row);
    cudaGetSymbolAddress((void**)&p_iu_cur, g_iu_cur);
    cudaGetSymbolAddress((void**)&p_iu_pk,  g_iu_pk);
    cudaGetSymbolAddress((void**)&p_ii_row, g_ii_row);
    cudaGetSymbolAddress((void**)&p_ii_cur, g_ii_cur);
    cudaGetSymbolAddress((void**)&p_ii_pk,  g_ii_pk);

    const int TB = 256;
    const int NB_NODE = NB_ENT + NB_USR;   // 18750

    // ---- CSR build (shared by both layers) ----
    zero_cnt_k<<<512, TB>>>(p_kg_cur, N_ENT, p_iu_cur, N_USERS, p_ii_cur, N_ENT);
    hist_k<<<1536, TB>>>(edge_index, inter_edge, p_kg_cur, p_iu_cur, p_ii_cur);
    scan3_k<<<3, 1024>>>(p_kg_cur, p_kg_row, p_iu_cur, p_iu_row, p_ii_cur, p_ii_row);
    scatter_k<<<1536, TB>>>(edge_index, edge_type, inter_edge, inter_w,
                            p_kg_cur, p_kg_pk, p_iu_cur, p_iu_pk, p_ii_cur, p_ii_pk);

    // ---- layer 1 ----
    gemm_k<<<N_ENT / 16, TB>>>(entity_emb, W_Q, p_P);
    node_k<0><<<NB_NODE, TB>>>(p_kg_row, p_kg_pk, p_ii_row, p_ii_pk, p_iu_row, p_iu_pk,
                               p_P, entity_emb, user_emb, rel_emb,
                               nullptr, nullptr, p_ent0, p_usr0);

    // ---- layer 2 (writes the 3-layer mean directly to out) ----
    gemm_k<<<N_ENT / 16, TB>>>(p_ent0, W_Q, p_P);
    node_k<1><<<NB_NODE, TB>>>(p_kg_row, p_kg_pk, p_ii_row, p_ii_pk, p_iu_row, p_iu_pk,
                               p_P, p_ent0, p_usr0, rel_emb,
                               entity_emb, user_emb, out_ent, out_usr);
}